// round 4
// baseline (speedup 1.0000x reference)
#include <cuda_runtime.h>
#include <cuda_fp16.h>
#include <cstdint>

#define B_DIM   512
#define IN_DIM  4096
#define OUT_DIM 11008
#define BK      64
#define NCHUNK  64          // IN_DIM / BK
#define TILE_M  80
#define NTILES  138         // 138*80 = 11040 >= 11008 (last tile: 48 valid rows)
#define THREADS 256

// SMEM layout (byte offsets from 1024-aligned base)
#define LUT_OFF 0           // 256 x 32 x 4B = 32KB, replicated LUT
#define XS_OFF  32768       // 2 stages x (512 rows x 128B) = 2 x 64KB
#define WF_OFF  163840      // 2 stages x (80 rows x 128B)  = 2 x 10KB
#define SMEM_BYTES (184320 + 1024)

__device__ __align__(16) __half g_xh[B_DIM * IN_DIM];   // fp16 x
__device__ uint32_t g_lut[256];                          // fp16 bits of exp LUT

// ---------------- helpers ----------------
__device__ __forceinline__ uint32_t smem_u32(const void* p) {
    uint32_t a;
    asm("{ .reg .u64 t; cvta.to.shared.u64 t, %1; cvt.u32.u64 %0, t; }" : "=r"(a) : "l"(p));
    return a;
}
__device__ __forceinline__ uint32_t sw128(uint32_t off) { return off ^ ((off >> 3) & 0x70); }
__device__ __forceinline__ uint32_t lds32(uint32_t a) {
    uint32_t v;
    asm("ld.shared.b32 %0, [%1];" : "=r"(v) : "r"(a));
    return v;
}
__device__ __forceinline__ void sts64(uint32_t a, uint32_t x, uint32_t y) {
    asm volatile("st.shared.v2.b32 [%0], {%1, %2};" :: "r"(a), "r"(x), "r"(y) : "memory");
}
__device__ __forceinline__ void cp16(uint32_t dst, const void* src) {
    asm volatile("cp.async.cg.shared.global [%0], [%1], 16;" :: "r"(dst), "l"(src) : "memory");
}
__device__ __forceinline__ void cp_commit() {
    asm volatile("cp.async.commit_group;" ::: "memory");
}
__device__ __forceinline__ void mma16816(float* c, const uint32_t* a, uint32_t b0, uint32_t b1) {
    asm volatile(
        "mma.sync.aligned.m16n8k16.row.col.f32.f16.f16.f32 "
        "{%0,%1,%2,%3}, {%4,%5,%6,%7}, {%8,%9}, {%0,%1,%2,%3};"
        : "+f"(c[0]), "+f"(c[1]), "+f"(c[2]), "+f"(c[3])
        : "r"(a[0]), "r"(a[1]), "r"(a[2]), "r"(a[3]), "r"(b0), "r"(b1));
}

// ---------------- prep: x fp32->fp16, exp LUT ----------------
__global__ void prep_kernel(const float* __restrict__ x,
                            const float* __restrict__ lmin,
                            const float* __restrict__ lmax) {
    int idx = blockIdx.x * blockDim.x + threadIdx.x;
    const int n4 = B_DIM * IN_DIM / 4;
    if (idx < n4) {
        float4 v = reinterpret_cast<const float4*>(x)[idx];
        __half2 a = __floats2half2_rn(v.x, v.y);
        __half2 b = __floats2half2_rn(v.z, v.w);
        uint2 w;
        w.x = *reinterpret_cast<uint32_t*>(&a);
        w.y = *reinterpret_cast<uint32_t*>(&b);
        reinterpret_cast<uint2*>(g_xh)[idx] = w;
    }
    if (blockIdx.x == 0 && threadIdx.x < 256) {
        float a = lmin[0], b = lmax[0];
        float nm = (255.0f - (float)threadIdx.x) / 254.0f;
        __half h = __float2half_rn(expf(fmaf(nm, b - a, a)));
        g_lut[threadIdx.x] = (uint32_t)__half_as_ushort(h);
    }
}

// ---------------- main GEMM: out[b][o] = (sum + bias[o]) * scale[o] ----------------
__global__ void __launch_bounds__(THREADS, 1)
qgemm_kernel(const int* __restrict__ stored, const int* __restrict__ sign,
             const float* __restrict__ scale, const float* __restrict__ bias,
             float* __restrict__ out) {
    extern __shared__ char smem_raw[];
    char* smem = (char*)(((uintptr_t)smem_raw + 1023) & ~(uintptr_t)1023);
    const uint32_t sb = smem_u32(smem);
    const int tid = threadIdx.x, wid = tid >> 5, lane = tid & 31;
    const int gid = lane >> 2, tig = lane & 3;
    const int o0 = blockIdx.x * TILE_M;
    const int n0 = wid * 64;

    // replicated LUT: slut[s*32 + lane]  (bank == lane: conflict-free)
    uint32_t* slut = (uint32_t*)(smem + LUT_OFF);
    for (int i = tid; i < 256 * 32; i += THREADS) slut[i] = g_lut[i >> 5];
    const uint32_t* lut_lane = slut + lane;

    // fp32 accumulators: warp tile M80 x N64 -> 5 mtiles x 8 ntiles x 4 floats
    float acc[5][8][4];
#pragma unroll
    for (int mt = 0; mt < 5; mt++)
#pragma unroll
        for (int nt = 0; nt < 8; nt++)
#pragma unroll
            for (int i = 0; i < 4; i++) acc[mt][nt][i] = 0.0f;

    // W int prefetch registers: 5 units of (4 stored + 4 sign)
    uint4 rs[5], rg[5];

    // per-thread dequant/load unit coords: u = tid + j*256 -> row = u>>4 (0..79), c = u&15
    int rowu[5], cu[5];
    long wbase[5];
#pragma unroll
    for (int j = 0; j < 5; j++) {
        int u = tid + j * 256;
        rowu[j] = u >> 4;
        cu[j] = u & 15;
        int row_g = o0 + rowu[j];
        if (row_g > OUT_DIM - 1) row_g = OUT_DIM - 1;   // clamp for last tile
        wbase[j] = (long)row_g * IN_DIM + cu[j] * 4;
    }

    // X cp.async coords: u = tid + j*256 -> b = u>>3 (0..511), seg = u&7 (16 per thread)
    // prologue: X(0) + W(0)
#pragma unroll
    for (int j = 0; j < 16; j++) {
        int u = tid + j * 256;
        int b = u >> 3, c = u & 7;
        cp16(sb + XS_OFF + sw128((uint32_t)(b * 128 + c * 16)),
             g_xh + (size_t)b * IN_DIM + c * 8);
    }
    cp_commit();
#pragma unroll
    for (int j = 0; j < 5; j++) {
        rs[j] = *(const uint4*)(stored + wbase[j]);
        rg[j] = *(const uint4*)(sign + wbase[j]);
    }
    __syncthreads();   // LUT ready

#pragma unroll 1
    for (int k = 0; k < NCHUNK; k++) {
        const int s = k & 1;
        const uint32_t xs = sb + XS_OFF + s * 65536;
        const uint32_t wf = sb + WF_OFF + s * 10240;

        // 1. issue cp.async for X(k+1) into the other stage
        if (k + 1 < NCHUNK) {
            const int K1 = (k + 1) * BK;
            const uint32_t xd = sb + XS_OFF + (1 - s) * 65536;
#pragma unroll
            for (int j = 0; j < 16; j++) {
                int u = tid + j * 256;
                int b = u >> 3, c = u & 7;
                cp16(xd + sw128((uint32_t)(b * 128 + c * 16)),
                     g_xh + (size_t)b * IN_DIM + K1 + c * 8);
            }
            cp_commit();
        }

        // 2. dequant W(k) regs -> WF[s]
#pragma unroll
        for (int j = 0; j < 5; j++) {
            uint4 s4 = rs[j], g4 = rg[j];
            uint32_t h0 = lut_lane[s4.x << 5] | (g4.x & 0x8000u);
            uint32_t h1 = lut_lane[s4.y << 5] | (g4.y & 0x8000u);
            uint32_t h2 = lut_lane[s4.z << 5] | (g4.z & 0x8000u);
            uint32_t h3 = lut_lane[s4.w << 5] | (g4.w & 0x8000u);
            sts64(wf + sw128((uint32_t)(rowu[j] * 128 + cu[j] * 8)),
                  h0 | (h1 << 16), h2 | (h3 << 16));
        }

        // 3. prefetch W(k+1) ints
        if (k + 1 < NCHUNK) {
            const int K1 = (k + 1) * BK;
#pragma unroll
            for (int j = 0; j < 5; j++) {
                rs[j] = *(const uint4*)(stored + wbase[j] + K1);
                rg[j] = *(const uint4*)(sign + wbase[j] + K1);
            }
        }

        // 4. wait for X(k) (leave X(k+1) in flight), 5. publish
        if (k + 1 < NCHUNK) asm volatile("cp.async.wait_group 1;" ::: "memory");
        else                asm volatile("cp.async.wait_group 0;" ::: "memory");
        __syncthreads();

        // 6. MMA: 4 k16 steps
#pragma unroll
        for (int kk = 0; kk < 4; kk++) {
            uint32_t a[5][4];
#pragma unroll
            for (int mt = 0; mt < 5; mt++) {
                uint32_t r0 = (uint32_t)((mt * 16 + gid) * 128 + kk * 32 + tig * 4);
                uint32_t r1 = (uint32_t)((mt * 16 + gid + 8) * 128 + kk * 32 + tig * 4);
                a[mt][0] = lds32(wf + sw128(r0));
                a[mt][1] = lds32(wf + sw128(r1));
                a[mt][2] = lds32(wf + sw128(r0 + 16));
                a[mt][3] = lds32(wf + sw128(r1 + 16));
            }
#pragma unroll
            for (int nt = 0; nt < 8; nt++) {
                uint32_t xb = (uint32_t)((n0 + nt * 8 + gid) * 128 + kk * 32 + tig * 4);
                uint32_t b0 = lds32(xs + sw128(xb));
                uint32_t b1 = lds32(xs + sw128(xb + 16));
#pragma unroll
                for (int mt = 0; mt < 5; mt++) mma16816(acc[mt][nt], a[mt], b0, b1);
            }
        }
        __syncthreads();   // everyone done reading stage s before it is rewritten
    }

    // ---------------- epilogue ----------------
#pragma unroll
    for (int mt = 0; mt < 5; mt++) {
        int o_lo = o0 + mt * 16 + gid;
        int o_hi = o_lo + 8;
        int cl = o_lo < OUT_DIM ? o_lo : OUT_DIM - 1;
        int ch = o_hi < OUT_DIM ? o_hi : OUT_DIM - 1;
        float blo = bias[cl], slo = scale[cl];
        float bhi = bias[ch], shi = scale[ch];
#pragma unroll
        for (int nt = 0; nt < 8; nt++) {
            int b = n0 + nt * 8 + tig * 2;
            float* p0 = out + (size_t)b * OUT_DIM;
            float* p1 = p0 + OUT_DIM;
            if (o_lo < OUT_DIM) {
                p0[o_lo] = (acc[mt][nt][0] + blo) * slo;
                p1[o_lo] = (acc[mt][nt][1] + blo) * slo;
            }
            if (o_hi < OUT_DIM) {
                p0[o_hi] = (acc[mt][nt][2] + bhi) * shi;
                p1[o_hi] = (acc[mt][nt][3] + bhi) * shi;
            }
        }
    }
}

extern "C" void kernel_launch(void* const* d_in, const int* in_sizes, int n_in,
                              void* d_out, int out_size) {
    const float* x      = (const float*)d_in[0];
    const int*   stored = (const int*)d_in[1];
    const int*   sign   = (const int*)d_in[2];
    const float* lmin   = (const float*)d_in[3];
    const float* lmax   = (const float*)d_in[4];
    const float* scale  = (const float*)d_in[5];
    const float* bias   = (const float*)d_in[6];
    float* out = (float*)d_out;

    prep_kernel<<<(B_DIM * IN_DIM / 4 + 255) / 256, 256>>>(x, lmin, lmax);

    cudaFuncSetAttribute(qgemm_kernel,
                         cudaFuncAttributeMaxDynamicSharedMemorySize, SMEM_BYTES);
    qgemm_kernel<<<NTILES, THREADS, SMEM_BYTES>>>(stored, sign, scale, bias, out);
}

// round 5
// speedup vs baseline: 1.1375x; 1.1375x over previous
#include <cuda_runtime.h>
#include <cuda_fp16.h>
#include <cstdint>

#define B_DIM   512
#define IN_DIM  4096
#define OUT_DIM 11008
#define BK      32
#define NCHUNK  128         // IN_DIM / BK
#define TILE_M  80
#define NTILES  138         // 138*80 = 11040 >= 11008
#define THREADS 256

// SMEM layout (byte offsets from 1024-aligned base)
#define LUT_OFF 0           // 256 x 32 x 4B = 32KB replicated LUT
#define XS_OFF  32768       // 3 stages x (512 rows x 64B) = 3 x 32KB
#define WS_OFF  131072      // 3 stages x (80 rows x 128B int32) = 3 x 10KB
#define WF_OFF  161792      // 2 stages x (80 rows x 64B fp16) = 2 x 5KB
#define SMEM_BYTES (172032 + 1024)

__device__ __align__(16) __half g_xh[B_DIM * IN_DIM];
__device__ uint32_t g_lut[256];

// ---------------- helpers ----------------
__device__ __forceinline__ uint32_t smem_u32(const void* p) {
    uint32_t a;
    asm("{ .reg .u64 t; cvta.to.shared.u64 t, %1; cvt.u32.u64 %0, t; }" : "=r"(a) : "l"(p));
    return a;
}
__device__ __forceinline__ uint32_t lds32(uint32_t a) {
    uint32_t v;
    asm("ld.shared.b32 %0, [%1];" : "=r"(v) : "r"(a));
    return v;
}
__device__ __forceinline__ void lds64(uint32_t a, uint32_t& x, uint32_t& y) {
    asm("ld.shared.v2.b32 {%0,%1}, [%2];" : "=r"(x), "=r"(y) : "r"(a));
}
__device__ __forceinline__ void sts32(uint32_t a, uint32_t v) {
    asm volatile("st.shared.b32 [%0], %1;" :: "r"(a), "r"(v) : "memory");
}
__device__ __forceinline__ void cp16(uint32_t dst, const void* src) {
    asm volatile("cp.async.cg.shared.global [%0], [%1], 16;" :: "r"(dst), "l"(src) : "memory");
}
__device__ __forceinline__ void cp8(uint32_t dst, const void* src) {
    asm volatile("cp.async.ca.shared.global [%0], [%1], 8;" :: "r"(dst), "l"(src) : "memory");
}
__device__ __forceinline__ void cp_commit() {
    asm volatile("cp.async.commit_group;" ::: "memory");
}
__device__ __forceinline__ void mma16816(float* c, const uint32_t* a, uint32_t b0, uint32_t b1) {
    asm volatile(
        "mma.sync.aligned.m16n8k16.row.col.f32.f16.f16.f32 "
        "{%0,%1,%2,%3}, {%4,%5,%6,%7}, {%8,%9}, {%0,%1,%2,%3};"
        : "+f"(c[0]), "+f"(c[1]), "+f"(c[2]), "+f"(c[3])
        : "r"(a[0]), "r"(a[1]), "r"(a[2]), "r"(a[3]), "r"(b0), "r"(b1));
}

// ---------------- prep: x fp32->fp16, exp LUT ----------------
__global__ void prep_kernel(const float* __restrict__ x,
                            const float* __restrict__ lmin,
                            const float* __restrict__ lmax) {
    int idx = blockIdx.x * blockDim.x + threadIdx.x;
    const int n4 = B_DIM * IN_DIM / 4;
    if (idx < n4) {
        float4 v = reinterpret_cast<const float4*>(x)[idx];
        __half2 a = __floats2half2_rn(v.x, v.y);
        __half2 b = __floats2half2_rn(v.z, v.w);
        uint2 w;
        w.x = *reinterpret_cast<uint32_t*>(&a);
        w.y = *reinterpret_cast<uint32_t*>(&b);
        reinterpret_cast<uint2*>(g_xh)[idx] = w;
    }
    if (blockIdx.x == 0 && threadIdx.x < 256) {
        float a = lmin[0], b = lmax[0];
        float nm = (255.0f - (float)threadIdx.x) / 254.0f;
        __half h = __float2half_rn(expf(fmaf(nm, b - a, a)));
        g_lut[threadIdx.x] = (uint32_t)__half_as_ushort(h);
    }
}

// ---------------- main GEMM ----------------
__global__ void __launch_bounds__(THREADS, 1)
qgemm_kernel(const int* __restrict__ stored, const int* __restrict__ sign,
             const float* __restrict__ scale, const float* __restrict__ bias,
             float* __restrict__ out) {
    extern __shared__ char smem_raw[];
    char* smem = (char*)(((uintptr_t)smem_raw + 1023) & ~(uintptr_t)1023);
    const uint32_t sb = smem_u32(smem);
    const int tid = threadIdx.x, wid = tid >> 5, lane = tid & 31;
    const int gid = lane >> 2, tig = lane & 3;
    const int o0 = blockIdx.x * TILE_M;
    const int n0 = wid * 64;

    // replicated LUT (bank == lane)
    uint32_t* slut = (uint32_t*)(smem + LUT_OFF);
    for (int i = tid; i < 256 * 32; i += THREADS) slut[i] = g_lut[i >> 5];
    const uint32_t* lut_lane = slut + lane;

    float acc[5][8][4];
#pragma unroll
    for (int mt = 0; mt < 5; mt++)
#pragma unroll
        for (int nt = 0; nt < 8; nt++)
#pragma unroll
            for (int i = 0; i < 4; i++) acc[mt][nt][i] = 0.0f;

    // per-thread frag-address constants: SW64 xor mask is gid-only
    const uint32_t xorm = (uint32_t)(((gid >> 1) & 3) << 4);
    uint32_t coff[4];
#pragma unroll
    for (int j = 0; j < 4; j++) coff[j] = (uint32_t)(j * 16) ^ xorm;
    uint32_t baseA[5], baseB[8];
#pragma unroll
    for (int mt = 0; mt < 5; mt++) baseA[mt] = (uint32_t)((mt * 16 + gid) * 64 + tig * 4);
#pragma unroll
    for (int nt = 0; nt < 8; nt++) baseB[nt] = (uint32_t)((n0 + nt * 8 + gid) * 64 + tig * 4);

    // W unit coords: u = tid + j*256 -> row (0..79), pair (0..15 of 2 ints)
    uint32_t woff[5], wsdst[5], wfdst[5];
#pragma unroll
    for (int j = 0; j < 5; j++) {
        int u = tid + j * 256, row = u >> 4, cp = u & 15;
        int rowg = o0 + row;
        if (rowg > OUT_DIM - 1) rowg = OUT_DIM - 1;
        woff[j]  = (uint32_t)rowg * IN_DIM + (uint32_t)(cp * 2);
        wsdst[j] = (uint32_t)(row * 128 + cp * 8);
        wfdst[j] = (uint32_t)(row * 64) + ((uint32_t)(cp * 4) ^ (uint32_t)(((row >> 1) & 3) << 4));
    }
    // X unit coords: u = tid + j*256 -> b (0..511), seg (0..3 of 16B)
    uint32_t xdst[8], xoff[8];
#pragma unroll
    for (int j = 0; j < 8; j++) {
        int u = tid + j * 256, b = u >> 2, sg = u & 3;
        xdst[j] = (uint32_t)(b * 64) + ((uint32_t)(sg * 16) ^ (uint32_t)(((b >> 1) & 3) << 4));
        xoff[j] = (uint32_t)b * IN_DIM + (uint32_t)(sg * 8);
    }

    // ---------------- prologue ----------------
#pragma unroll
    for (int j = 0; j < 8; j++) cp16(sb + XS_OFF + xdst[j], g_xh + xoff[j]);
    cp_commit();                                            // X(0) -> stage 0
#pragma unroll
    for (int j = 0; j < 5; j++) cp8(sb + WS_OFF + wsdst[j], stored + woff[j]);
    cp_commit();                                            // Ws(0) -> stage 0
#pragma unroll
    for (int j = 0; j < 5; j++) cp8(sb + WS_OFF + 10240 + wsdst[j], stored + woff[j] + BK);
    cp_commit();                                            // Ws(1) -> stage 1
    uint2 rg[5];
#pragma unroll
    for (int j = 0; j < 5; j++) rg[j] = *(const uint2*)(sign + woff[j]);
    asm volatile("cp.async.wait_group 1;" ::: "memory");    // X(0), Ws(0) done
    __syncthreads();                                        // publish (+ LUT)
    {   // dequant(0) -> Wf[0]
        const uint32_t wsb = sb + WS_OFF, wfb = sb + WF_OFF;
#pragma unroll
        for (int j = 0; j < 5; j++) {
            uint32_t s0, s1;
            lds64(wsb + wsdst[j], s0, s1);
            uint32_t h0 = lut_lane[s0 << 5] | (rg[j].x & 0x8000u);
            uint32_t h1 = lut_lane[s1 << 5] | (rg[j].y & 0x8000u);
            sts32(wfb + wfdst[j], h0 | (h1 << 16));
        }
    }

    int s3 = 0, s3b = 1, s3c = 2;   // k%3, (k+1)%3, (k+2)%3
#pragma unroll 1
    for (int k = 0; k < NCHUNK; k++) {
        // issue next-stage copies (pre-sync: safe under 3-stage rotation)
        if (k + 1 < NCHUNK) {
            const uint32_t K1 = (uint32_t)(k + 1) * BK;
            const uint32_t xd = sb + XS_OFF + (uint32_t)s3b * 32768;
#pragma unroll
            for (int j = 0; j < 8; j++) cp16(xd + xdst[j], g_xh + xoff[j] + K1);
            cp_commit();
        }
        if (k + 2 < NCHUNK) {
            const uint32_t K2 = (uint32_t)(k + 2) * BK;
            const uint32_t wd = sb + WS_OFF + (uint32_t)s3c * 10240;
#pragma unroll
            for (int j = 0; j < 5; j++) cp8(wd + wsdst[j], stored + woff[j] + K2);
            cp_commit();
        }
        if (k + 1 < NCHUNK) {
            const uint32_t K1 = (uint32_t)(k + 1) * BK;
#pragma unroll
            for (int j = 0; j < 5; j++) rg[j] = *(const uint2*)(sign + woff[j] + K1);
        }
        if (k + 2 < NCHUNK)      asm volatile("cp.async.wait_group 2;" ::: "memory");
        else if (k + 1 < NCHUNK) asm volatile("cp.async.wait_group 1;" ::: "memory");
        else                     asm volatile("cp.async.wait_group 0;" ::: "memory");
        __syncthreads();   // publish X(k), Ws(k+1), Wf(k)

        // MMA(k)
        {
            const uint32_t wfs = sb + WF_OFF + (uint32_t)(k & 1) * 5120;
            const uint32_t xss = sb + XS_OFF + (uint32_t)s3 * 32768;
#pragma unroll
            for (int kk = 0; kk < 2; kk++) {
                uint32_t a[5][4];
#pragma unroll
                for (int mt = 0; mt < 5; mt++) {
                    a[mt][0] = lds32(wfs + baseA[mt] + coff[2 * kk]);
                    a[mt][1] = lds32(wfs + baseA[mt] + 512 + coff[2 * kk]);
                    a[mt][2] = lds32(wfs + baseA[mt] + coff[2 * kk + 1]);
                    a[mt][3] = lds32(wfs + baseA[mt] + 512 + coff[2 * kk + 1]);
                }
#pragma unroll
                for (int nt = 0; nt < 8; nt++) {
                    uint32_t b0 = lds32(xss + baseB[nt] + coff[2 * kk]);
                    uint32_t b1 = lds32(xss + baseB[nt] + coff[2 * kk + 1]);
#pragma unroll
                    for (int mt = 0; mt < 5; mt++) mma16816(acc[mt][nt], a[mt], b0, b1);
                }
            }
        }

        // dequant(k+1) -> Wf[(k+1)&1]
        if (k + 1 < NCHUNK) {
            const uint32_t wsb = sb + WS_OFF + (uint32_t)s3b * 10240;
            const uint32_t wfb = sb + WF_OFF + (uint32_t)((k + 1) & 1) * 5120;
#pragma unroll
            for (int j = 0; j < 5; j++) {
                uint32_t s0, s1;
                lds64(wsb + wsdst[j], s0, s1);
                uint32_t h0 = lut_lane[s0 << 5] | (rg[j].x & 0x8000u);
                uint32_t h1 = lut_lane[s1 << 5] | (rg[j].y & 0x8000u);
                sts32(wfb + wfdst[j], h0 | (h1 << 16));
            }
        }

        int t = s3; s3 = s3b; s3b = s3c; s3c = t;
    }

    // ---------------- epilogue ----------------
#pragma unroll
    for (int mt = 0; mt < 5; mt++) {
        int o_lo = o0 + mt * 16 + gid;
        int o_hi = o_lo + 8;
        int cl = o_lo < OUT_DIM ? o_lo : OUT_DIM - 1;
        int ch = o_hi < OUT_DIM ? o_hi : OUT_DIM - 1;
        float blo = bias[cl], slo = scale[cl];
        float bhi = bias[ch], shi = scale[ch];
#pragma unroll
        for (int nt = 0; nt < 8; nt++) {
            int b = n0 + nt * 8 + tig * 2;
            float* p0 = out + (size_t)b * OUT_DIM;
            float* p1 = p0 + OUT_DIM;
            if (o_lo < OUT_DIM) {
                p0[o_lo] = (acc[mt][nt][0] + blo) * slo;
                p1[o_lo] = (acc[mt][nt][1] + blo) * slo;
            }
            if (o_hi < OUT_DIM) {
                p0[o_hi] = (acc[mt][nt][2] + bhi) * shi;
                p1[o_hi] = (acc[mt][nt][3] + bhi) * shi;
            }
        }
    }
}

extern "C" void kernel_launch(void* const* d_in, const int* in_sizes, int n_in,
                              void* d_out, int out_size) {
    const float* x      = (const float*)d_in[0];
    const int*   stored = (const int*)d_in[1];
    const int*   sign   = (const int*)d_in[2];
    const float* lmin   = (const float*)d_in[3];
    const float* lmax   = (const float*)d_in[4];
    const float* scale  = (const float*)d_in[5];
    const float* bias   = (const float*)d_in[6];
    float* out = (float*)d_out;

    prep_kernel<<<(B_DIM * IN_DIM / 4 + 255) / 256, 256>>>(x, lmin, lmax);

    cudaFuncSetAttribute(qgemm_kernel,
                         cudaFuncAttributeMaxDynamicSharedMemorySize, SMEM_BYTES);
    qgemm_kernel<<<NTILES, THREADS, SMEM_BYTES>>>(stored, sign, scale, bias, out);
}